// round 9
// baseline (speedup 1.0000x reference)
#include <cuda_runtime.h>
#include <cuda_fp16.h>
#include <math.h>
#include <stdint.h>

#define VOCAB 50257
#define DHID  128
#define NTOK  1024
#define NFREQ 256
#define SEQ   512

// ---------------- device scratch ----------------
__device__ __align__(16) float g_xr[NTOK*DHID];
__device__ __align__(16) float g_xi[NTOK*DHID];
__device__ __align__(16) float g_xc[NTOK*DHID];
__device__ __align__(16) float g_cs[NTOK*NFREQ];
__device__ __align__(16) float g_ss[NTOK*NFREQ];
__device__ __align__(16) __half g_Wr16[VOCAB*DHID];
__device__ __align__(16) __half g_Wi16[VOCAB*DHID];
__device__ __align__(16) __half g_Wni16[VOCAB*DHID];   // -Wi (exact negation of fp16)
__device__ __align__(16) __half g_Ar16[NTOK*DHID];
__device__ __align__(16) __half g_Ai16[NTOK*DHID];

// ---------------- small kernels ----------------
__global__ void embed_kernel(const int* __restrict__ ids, const float* __restrict__ emb) {
    int t = blockIdx.x, d = threadIdx.x;
    int id = ids[t];
    g_xr[t*DHID + d] = emb[(size_t)id*256 + d];
    g_xi[t*DHID + d] = emb[(size_t)id*256 + 128 + d];
}

__global__ void wsplit_kernel(const float* __restrict__ Wr, const float* __restrict__ Wi) {
    int i = blockIdx.x*256 + threadIdx.x;
    if (i < VOCAB*DHID) {
        g_Wr16[i] = __float2half(Wr[i]);
        __half w = __float2half(Wi[i]);
        g_Wi16[i] = w;
        g_Wni16[i] = __hneg(w);
    }
}

__global__ void asplit_kernel() {
    int i = blockIdx.x*256 + threadIdx.x;
    g_Ar16[i] = __float2half(g_xr[i]);
    g_Ai16[i] = __float2half(g_xi[i]);
}

__global__ void xc_kernel(const float* __restrict__ cwl, const float* __restrict__ cbl) {
    __shared__ __align__(16) float xs[8*256];
    int tid = threadIdx.x, tBase = blockIdx.x*8;
    for (int i = tid; i < 8*256; i += 128) {
        int t = i >> 8, k = i & 255;
        xs[i] = (k < 128) ? g_xr[(tBase+t)*DHID + k] : g_xi[(tBase+t)*DHID + k - 128];
    }
    __syncthreads();
    int d = tid;
    float cb = cbl[d], acc[8];
    #pragma unroll
    for (int t = 0; t < 8; t++) acc[t] = cb;
    for (int k = 0; k < 256; k += 4) {
        float4 w = *reinterpret_cast<const float4*>(&cwl[d*256 + k]);
        #pragma unroll
        for (int t = 0; t < 8; t++) {
            acc[t] = fmaf(w.x, xs[t*256+k+0], acc[t]);
            acc[t] = fmaf(w.y, xs[t*256+k+1], acc[t]);
            acc[t] = fmaf(w.z, xs[t*256+k+2], acc[t]);
            acc[t] = fmaf(w.w, xs[t*256+k+3], acc[t]);
        }
    }
    #pragma unroll
    for (int t = 0; t < 8; t++) g_xc[(tBase+t)*DHID + d] = acc[t];
}

__global__ void theta_kernel(const float* __restrict__ Wl, const float* __restrict__ Bpl,
                             const float* __restrict__ acl, const float* __restrict__ asl) {
    __shared__ __align__(16) float xs[16*128];
    const float KSCALE = (float)(4096.0 / 6.283185307179586);
    const float ASTEP  = (float)(6.283185307179586 / 4096.0);
    const float PHI_F  = 1.6180339887498948f;
    int tid = threadIdx.x, warp = tid >> 5, lane = tid & 31;
    int n = blockIdx.x*4 + warp;
    int tBase = blockIdx.y*16;
    for (int i = tid; i < 16*128; i += 128)
        xs[i] = g_xc[(tBase + (i >> 7))*DHID + (i & 127)];
    __syncthreads();
    int d0 = lane*4;
    float4 w4  = *reinterpret_cast<const float4*>(&Wl [n*DHID + d0]);
    float4 bp4 = *reinterpret_cast<const float4*>(&Bpl[n*DHID + d0]);
    float4 ac4 = *reinterpret_cast<const float4*>(&acl[n*DHID + d0]);
    float4 as4 = *reinterpret_cast<const float4*>(&asl[n*DHID + d0]);
    float4 rw;
    rw.x = 1.0f/(1.0f+fabsf(w4.x)); rw.y = 1.0f/(1.0f+fabsf(w4.y));
    rw.z = 1.0f/(1.0f+fabsf(w4.z)); rw.w = 1.0f/(1.0f+fabsf(w4.w));
    for (int tt = 0; tt < 16; tt++) {
        int tok = tBase + tt;
        float tpos = (float)(tok & (SEQ-1)) * PHI_F;
        float4 x4 = *reinterpret_cast<const float4*>(&xs[tt*128 + d0]);
        float cs = 0.f, ss = 0.f, sv, cv, th; int idx;
        th = fmaf(x4.x, rw.x, bp4.x) + tpos;
        idx = __float2int_rd(th * KSCALE) & 4095;
        __sincosf((float)idx * ASTEP, &sv, &cv);
        cs = fmaf(cv, ac4.x, cs); ss = fmaf(sv, as4.x, ss);
        th = fmaf(x4.y, rw.y, bp4.y) + tpos;
        idx = __float2int_rd(th * KSCALE) & 4095;
        __sincosf((float)idx * ASTEP, &sv, &cv);
        cs = fmaf(cv, ac4.y, cs); ss = fmaf(sv, as4.y, ss);
        th = fmaf(x4.z, rw.z, bp4.z) + tpos;
        idx = __float2int_rd(th * KSCALE) & 4095;
        __sincosf((float)idx * ASTEP, &sv, &cv);
        cs = fmaf(cv, ac4.z, cs); ss = fmaf(sv, as4.z, ss);
        th = fmaf(x4.w, rw.w, bp4.w) + tpos;
        idx = __float2int_rd(th * KSCALE) & 4095;
        __sincosf((float)idx * ASTEP, &sv, &cv);
        cs = fmaf(cv, ac4.w, cs); ss = fmaf(sv, as4.w, ss);
        #pragma unroll
        for (int off = 16; off > 0; off >>= 1) {
            cs += __shfl_down_sync(0xffffffffu, cs, off);
            ss += __shfl_down_sync(0xffffffffu, ss, off);
        }
        if (lane == 0) { g_cs[tok*NFREQ + n] = cs; g_ss[tok*NFREQ + n] = ss; }
    }
}

__global__ void op_kernel(const float* __restrict__ oprl, const float* __restrict__ opil) {
    __shared__ __align__(16) float cs_s[8*256];
    __shared__ __align__(16) float ss_s[8*256];
    int tid = threadIdx.x, tBase = blockIdx.x*8;
    for (int i = tid; i < 8*256; i += 128) {
        int t = i >> 8, k = i & 255;
        cs_s[i] = g_cs[(tBase+t)*NFREQ + k];
        ss_s[i] = g_ss[(tBase+t)*NFREQ + k];
    }
    __syncthreads();
    int d = tid;
    float accr[8], acci[8];
    #pragma unroll
    for (int t = 0; t < 8; t++) { accr[t] = 0.f; acci[t] = 0.f; }
    for (int k = 0; k < 256; k += 4) {
        float4 wr = *reinterpret_cast<const float4*>(&oprl[d*256 + k]);
        float4 wi = *reinterpret_cast<const float4*>(&opil[d*256 + k]);
        #pragma unroll
        for (int t = 0; t < 8; t++) {
            accr[t] = fmaf(wr.x, cs_s[t*256+k+0], accr[t]);
            accr[t] = fmaf(wr.y, cs_s[t*256+k+1], accr[t]);
            accr[t] = fmaf(wr.z, cs_s[t*256+k+2], accr[t]);
            accr[t] = fmaf(wr.w, cs_s[t*256+k+3], accr[t]);
            acci[t] = fmaf(wi.x, ss_s[t*256+k+0], acci[t]);
            acci[t] = fmaf(wi.y, ss_s[t*256+k+1], acci[t]);
            acci[t] = fmaf(wi.z, ss_s[t*256+k+2], acci[t]);
            acci[t] = fmaf(wi.w, ss_s[t*256+k+3], acci[t]);
        }
    }
    #pragma unroll
    for (int t = 0; t < 8; t++) {
        float vr = accr[t], vi = acci[t];
        g_xr[(tBase+t)*DHID + d] = vr / (1.0f + expf(-vr));
        g_xi[(tBase+t)*DHID + d] = vi / (1.0f + expf(-vi));
    }
}

// ---------------- vocab GEMM: single-pass fp16, no-XOR inner loop ----------------
// CTA tile: M=128 x N=64, K=128. 8 warps = 4m x 2n; warp tile 32x32 (mf=2, nf=4).
// A (Ar, Ai) resident; B (Wr, Wi, -Wi) double-buffered via cp.async.
// lr = Ar*Wr + Ai*(-Wi) ; li = Ai*Wr + Ar*Wi
#define ROWB   272
#define A_MTX  (128*ROWB)        // 34816
#define B_MTX  (64*ROWB)         // 17408
#define B_BUF  (3*B_MTX)         // 52224
#define SMEM_A (2*A_MTX)         // 69632
#define GEMM_SMEM (SMEM_A + 2*B_BUF)  // 174080
#define TILE_N   64
#define NT_TOT   786
#define CHUNKS   18
#define NT_CHUNK 44

__device__ __forceinline__ void mma_f16(float c[4], const uint32_t a[4], const uint32_t b[2]) {
    asm volatile(
        "mma.sync.aligned.m16n8k16.row.col.f32.f16.f16.f32 "
        "{%0,%1,%2,%3}, {%4,%5,%6,%7}, {%8,%9}, {%0,%1,%2,%3};\n"
        : "+f"(c[0]), "+f"(c[1]), "+f"(c[2]), "+f"(c[3])
        : "r"(a[0]), "r"(a[1]), "r"(a[2]), "r"(a[3]), "r"(b[0]), "r"(b[1]));
}
__device__ __forceinline__ void ldsm_x4(uint32_t r[4], uint32_t addr) {
    asm volatile("ldmatrix.sync.aligned.m8n8.x4.shared.b16 {%0,%1,%2,%3}, [%4];\n"
                 : "=r"(r[0]), "=r"(r[1]), "=r"(r[2]), "=r"(r[3]) : "r"(addr));
}
__device__ __forceinline__ void cp16(uint32_t dst, const void* src, int sz) {
    asm volatile("cp.async.cg.shared.global [%0], [%1], 16, %2;\n"
                 :: "r"(dst), "l"(src), "r"(sz));
}
__device__ __forceinline__ void cp_commit() { asm volatile("cp.async.commit_group;\n"); }
__device__ __forceinline__ void cp_wait0()  { asm volatile("cp.async.wait_group 0;\n"); }

__device__ __forceinline__ void prefetch_b(uint32_t dstBase, int nBase, int tid) {
    // 3 matrices x 64 rows x 16 chunks(16B) = 3072 chunks; 12 per thread
    #pragma unroll
    for (int j = 0; j < 12; j++) {
        int idx = tid + j*256;
        int mtx = idx >> 10;
        int rem = idx & 1023;
        int r = rem >> 4, c = rem & 15;
        int v = nBase + r;
        int sz = (v < VOCAB) ? 16 : 0;
        int vc = (v < VOCAB) ? v : (VOCAB-1);
        const __half* s = (mtx == 0) ? g_Wr16 : (mtx == 1) ? g_Wi16 : g_Wni16;
        cp16(dstBase + mtx*B_MTX + r*ROWB + c*16,
             (const char*)(s + (size_t)vc*DHID) + c*16, sz);
    }
}

__global__ void __launch_bounds__(256, 1) gemm_hmma(float* __restrict__ out) {
    extern __shared__ __align__(16) char sm[];
    uint32_t sbase;
    asm("{ .reg .u64 t; cvta.to.shared.u64 t, %1; cvt.u32.u64 %0, t; }" : "=r"(sbase) : "l"(sm));

    const int tid = threadIdx.x;
    const int mBase = blockIdx.y * 128;

    // ---- A: Ar, Ai via cp.async ----
    #pragma unroll
    for (int j = 0; j < 16; j++) {
        int idx = tid + j*256;
        int mtx = idx >> 11;
        int rem = idx & 2047;
        int r = rem >> 4, c = rem & 15;
        const __half* s = (mtx == 0) ? g_Ar16 : g_Ai16;
        cp16(sbase + mtx*A_MTX + r*ROWB + c*16,
             (const char*)(s + (size_t)(mBase + r)*DHID) + c*16, 16);
    }

    const int ntStart = blockIdx.x * NT_CHUNK;
    int ntEnd = ntStart + NT_CHUNK; if (ntEnd > NT_TOT) ntEnd = NT_TOT;
    const int T = ntEnd - ntStart;
    if (T <= 0) return;

    prefetch_b(sbase + SMEM_A, ntStart*TILE_N, tid);
    cp_commit();

    const int warp = tid >> 5, lane = tid & 31;
    const int wm = warp >> 1, wn = warp & 1;
    const int g = lane >> 2, tg = lane & 3;

    // ldmatrix lane-address bases (verified mappings)
    uint32_t aB[2][2];   // [Ar/Ai][mf]
    {
        const int arow = (lane & 7) + (lane & 8);
        const int acol = (lane & 16) ? 16 : 0;
        #pragma unroll
        for (int mtx = 0; mtx < 2; mtx++)
            #pragma unroll
            for (int mf = 0; mf < 2; mf++)
                aB[mtx][mf] = sbase + mtx*A_MTX + (wm*32 + mf*16 + arow)*ROWB + acol;
    }
    uint32_t bB[3][2];   // [Wr/Wi/-Wi][pair] ; pair p covers nf=2p,2p+1
    {
        const int brow = (lane & 7) + ((lane & 16) ? 8 : 0);
        const int bcol = (lane & 8) ? 16 : 0;
        #pragma unroll
        for (int mtx = 0; mtx < 3; mtx++)
            #pragma unroll
            for (int p = 0; p < 2; p++)
                bB[mtx][p] = sbase + SMEM_A + mtx*B_MTX + (wn*32 + p*16 + brow)*ROWB + bcol;
    }

    for (int t = 0; t < T; t++) {
        const int cur = t & 1;
        const uint32_t bOffBuf = (uint32_t)cur*B_BUF;
        cp_wait0();
        __syncthreads();
        if (t + 1 < T) {
            prefetch_b(sbase + SMEM_A + (cur^1)*B_BUF, (ntStart + t + 1)*TILE_N, tid);
            cp_commit();
        }

        float acc[2][2][4][4];   // [lr/li][mf][nf][q]
        #pragma unroll
        for (int o = 0; o < 2; o++)
            #pragma unroll
            for (int mf = 0; mf < 2; mf++)
                #pragma unroll
                for (int nf = 0; nf < 4; nf++)
                    #pragma unroll
                    for (int q = 0; q < 4; q++) acc[o][mf][nf][q] = 0.f;

        #pragma unroll 2
        for (int ks = 0; ks < 8; ks++) {
            const uint32_t kb = ks*32;
            uint32_t Ar[2][4], Ai[2][4];
            #pragma unroll
            for (int mf = 0; mf < 2; mf++) {
                ldsm_x4(Ar[mf], aB[0][mf] + kb);
                ldsm_x4(Ai[mf], aB[1][mf] + kb);
            }
            uint32_t Wr[2][4], Wi[2][4], Wn[2][4];
            #pragma unroll
            for (int p = 0; p < 2; p++) {
                ldsm_x4(Wr[p], bB[0][p] + bOffBuf + kb);
                ldsm_x4(Wi[p], bB[1][p] + bOffBuf + kb);
                ldsm_x4(Wn[p], bB[2][p] + bOffBuf + kb);
            }
            // pure mma stream, no register mutation
            #pragma unroll
            for (int mf = 0; mf < 2; mf++)
                #pragma unroll
                for (int nf = 0; nf < 4; nf++)
                    mma_f16(acc[0][mf][nf], Ar[mf], &Wr[nf>>1][(nf&1)*2]);   // lr += Ar*Wr
            #pragma unroll
            for (int mf = 0; mf < 2; mf++)
                #pragma unroll
                for (int nf = 0; nf < 4; nf++)
                    mma_f16(acc[1][mf][nf], Ai[mf], &Wr[nf>>1][(nf&1)*2]);   // li += Ai*Wr
            #pragma unroll
            for (int mf = 0; mf < 2; mf++)
                #pragma unroll
                for (int nf = 0; nf < 4; nf++)
                    mma_f16(acc[0][mf][nf], Ai[mf], &Wn[nf>>1][(nf&1)*2]);   // lr += Ai*(-Wi)
            #pragma unroll
            for (int mf = 0; mf < 2; mf++)
                #pragma unroll
                for (int nf = 0; nf < 4; nf++)
                    mma_f16(acc[1][mf][nf], Ar[mf], &Wi[nf>>1][(nf&1)*2]);   // li += Ar*Wi
        }

        // epilogue (scalar stores: VOCAB odd -> only 4B alignment guaranteed)
        const int nBase = (ntStart + t)*TILE_N;
        #pragma unroll
        for (int mf = 0; mf < 2; mf++) {
            const int row = mBase + wm*32 + mf*16 + g;
            #pragma unroll
            for (int nf = 0; nf < 4; nf++) {
                const int col = nBase + wn*32 + nf*8 + 2*tg;
                float* o0 = out + (size_t)row*VOCAB + col;
                float* o1 = o0 + (size_t)8*VOCAB;
                float lr0 = acc[0][mf][nf][0], li0 = acc[1][mf][nf][0];
                float lr1 = acc[0][mf][nf][1], li1 = acc[1][mf][nf][1];
                float lr2 = acc[0][mf][nf][2], li2 = acc[1][mf][nf][2];
                float lr3 = acc[0][mf][nf][3], li3 = acc[1][mf][nf][3];
                if (col < VOCAB) {
                    o0[0] = sqrtf(fmaf(lr0,lr0,fmaf(li0,li0,1e-8f)));
                    o1[0] = sqrtf(fmaf(lr2,lr2,fmaf(li2,li2,1e-8f)));
                }
                if (col + 1 < VOCAB) {
                    o0[1] = sqrtf(fmaf(lr1,lr1,fmaf(li1,li1,1e-8f)));
                    o1[1] = sqrtf(fmaf(lr3,lr3,fmaf(li3,li3,1e-8f)));
                }
            }
        }
        __syncthreads();
    }
}

// ---------------- launch ----------------
extern "C" void kernel_launch(void* const* d_in, const int* in_sizes, int n_in,
                              void* d_out, int out_size) {
    const int*   ids  = (const int*)  d_in[0];
    const float* emb  = (const float*)d_in[1];
    const float* cw   = (const float*)d_in[2];
    const float* cb   = (const float*)d_in[3];
    const float* W    = (const float*)d_in[4];
    const float* Bp   = (const float*)d_in[5];
    const float* acos_= (const float*)d_in[6];
    const float* asin_= (const float*)d_in[7];
    const float* opr  = (const float*)d_in[8];
    const float* opi  = (const float*)d_in[9];
    const float* Wr   = (const float*)d_in[10];
    const float* Wi   = (const float*)d_in[11];
    float* out = (float*)d_out;

    cudaFuncSetAttribute(gemm_hmma, cudaFuncAttributeMaxDynamicSharedMemorySize, GEMM_SMEM);

    embed_kernel<<<NTOK, 128>>>(ids, emb);
    wsplit_kernel<<<(VOCAB*DHID + 255)/256, 256>>>(Wr, Wi);

    for (int l = 0; l < 2; l++) {
        xc_kernel<<<NTOK/8, 128>>>(cw + (size_t)l*DHID*2*DHID, cb + (size_t)l*DHID);
        dim3 tg(NFREQ/4, NTOK/16);
        theta_kernel<<<tg, 128>>>(W + (size_t)l*NFREQ*DHID, Bp + (size_t)l*NFREQ*DHID,
                                  acos_ + (size_t)l*NFREQ*DHID, asin_ + (size_t)l*NFREQ*DHID);
        op_kernel<<<NTOK/8, 128>>>(opr + (size_t)l*DHID*NFREQ, opi + (size_t)l*DHID*NFREQ);
    }

    asplit_kernel<<<NTOK*DHID/256, 256>>>();
    gemm_hmma<<<dim3(CHUNKS, 8), 256, GEMM_SMEM>>>(out);
}

// round 10
// speedup vs baseline: 1.0526x; 1.0526x over previous
#include <cuda_runtime.h>
#include <cuda_fp16.h>
#include <math.h>
#include <stdint.h>

#define VOCAB 50257
#define DHID  128
#define NTOK  1024
#define NFREQ 256
#define SEQ   512

// ---------------- device scratch ----------------
__device__ __align__(16) float g_xr[NTOK*DHID];
__device__ __align__(16) float g_xi[NTOK*DHID];
__device__ __align__(16) float g_xc[NTOK*DHID];
__device__ __align__(16) float g_cs[NTOK*NFREQ];
__device__ __align__(16) float g_ss[NTOK*NFREQ];
__device__ __align__(16) __half g_Wr16[VOCAB*DHID];
__device__ __align__(16) __half g_Wi16[VOCAB*DHID];
__device__ __align__(16) __half g_Ar16[NTOK*DHID];
__device__ __align__(16) __half g_Ai16[NTOK*DHID];

// ---------------- small kernels ----------------
__global__ void embed_kernel(const int* __restrict__ ids, const float* __restrict__ emb) {
    int t = blockIdx.x, d = threadIdx.x;
    int id = ids[t];
    g_xr[t*DHID + d] = emb[(size_t)id*256 + d];
    g_xi[t*DHID + d] = emb[(size_t)id*256 + 128 + d];
}

__global__ void wsplit_kernel(const float* __restrict__ Wr, const float* __restrict__ Wi) {
    int i = blockIdx.x*256 + threadIdx.x;
    if (i < VOCAB*DHID) {
        g_Wr16[i] = __float2half(Wr[i]);
        g_Wi16[i] = __float2half(Wi[i]);
    }
}

__global__ void asplit_kernel() {
    int i = blockIdx.x*256 + threadIdx.x;
    g_Ar16[i] = __float2half(g_xr[i]);
    g_Ai16[i] = __float2half(g_xi[i]);
}

__global__ void xc_kernel(const float* __restrict__ cwl, const float* __restrict__ cbl) {
    __shared__ __align__(16) float xs[8*256];
    int tid = threadIdx.x, tBase = blockIdx.x*8;
    for (int i = tid; i < 8*256; i += 128) {
        int t = i >> 8, k = i & 255;
        xs[i] = (k < 128) ? g_xr[(tBase+t)*DHID + k] : g_xi[(tBase+t)*DHID + k - 128];
    }
    __syncthreads();
    int d = tid;
    float cb = cbl[d], acc[8];
    #pragma unroll
    for (int t = 0; t < 8; t++) acc[t] = cb;
    for (int k = 0; k < 256; k += 4) {
        float4 w = *reinterpret_cast<const float4*>(&cwl[d*256 + k]);
        #pragma unroll
        for (int t = 0; t < 8; t++) {
            acc[t] = fmaf(w.x, xs[t*256+k+0], acc[t]);
            acc[t] = fmaf(w.y, xs[t*256+k+1], acc[t]);
            acc[t] = fmaf(w.z, xs[t*256+k+2], acc[t]);
            acc[t] = fmaf(w.w, xs[t*256+k+3], acc[t]);
        }
    }
    #pragma unroll
    for (int t = 0; t < 8; t++) g_xc[(tBase+t)*DHID + d] = acc[t];
}

__global__ void theta_kernel(const float* __restrict__ Wl, const float* __restrict__ Bpl,
                             const float* __restrict__ acl, const float* __restrict__ asl) {
    __shared__ __align__(16) float xs[16*128];
    const float KSCALE = (float)(4096.0 / 6.283185307179586);
    const float ASTEP  = (float)(6.283185307179586 / 4096.0);
    const float PHI_F  = 1.6180339887498948f;
    int tid = threadIdx.x, warp = tid >> 5, lane = tid & 31;
    int n = blockIdx.x*4 + warp;
    int tBase = blockIdx.y*16;
    for (int i = tid; i < 16*128; i += 128)
        xs[i] = g_xc[(tBase + (i >> 7))*DHID + (i & 127)];
    __syncthreads();
    int d0 = lane*4;
    float4 w4  = *reinterpret_cast<const float4*>(&Wl [n*DHID + d0]);
    float4 bp4 = *reinterpret_cast<const float4*>(&Bpl[n*DHID + d0]);
    float4 ac4 = *reinterpret_cast<const float4*>(&acl[n*DHID + d0]);
    float4 as4 = *reinterpret_cast<const float4*>(&asl[n*DHID + d0]);
    float4 rw;
    rw.x = 1.0f/(1.0f+fabsf(w4.x)); rw.y = 1.0f/(1.0f+fabsf(w4.y));
    rw.z = 1.0f/(1.0f+fabsf(w4.z)); rw.w = 1.0f/(1.0f+fabsf(w4.w));
    for (int tt = 0; tt < 16; tt++) {
        int tok = tBase + tt;
        float tpos = (float)(tok & (SEQ-1)) * PHI_F;
        float4 x4 = *reinterpret_cast<const float4*>(&xs[tt*128 + d0]);
        float cs = 0.f, ss = 0.f, sv, cv, th; int idx;
        th = fmaf(x4.x, rw.x, bp4.x) + tpos;
        idx = __float2int_rd(th * KSCALE) & 4095;
        __sincosf((float)idx * ASTEP, &sv, &cv);
        cs = fmaf(cv, ac4.x, cs); ss = fmaf(sv, as4.x, ss);
        th = fmaf(x4.y, rw.y, bp4.y) + tpos;
        idx = __float2int_rd(th * KSCALE) & 4095;
        __sincosf((float)idx * ASTEP, &sv, &cv);
        cs = fmaf(cv, ac4.y, cs); ss = fmaf(sv, as4.y, ss);
        th = fmaf(x4.z, rw.z, bp4.z) + tpos;
        idx = __float2int_rd(th * KSCALE) & 4095;
        __sincosf((float)idx * ASTEP, &sv, &cv);
        cs = fmaf(cv, ac4.z, cs); ss = fmaf(sv, as4.z, ss);
        th = fmaf(x4.w, rw.w, bp4.w) + tpos;
        idx = __float2int_rd(th * KSCALE) & 4095;
        __sincosf((float)idx * ASTEP, &sv, &cv);
        cs = fmaf(cv, ac4.w, cs); ss = fmaf(sv, as4.w, ss);
        #pragma unroll
        for (int off = 16; off > 0; off >>= 1) {
            cs += __shfl_down_sync(0xffffffffu, cs, off);
            ss += __shfl_down_sync(0xffffffffu, ss, off);
        }
        if (lane == 0) { g_cs[tok*NFREQ + n] = cs; g_ss[tok*NFREQ + n] = ss; }
    }
}

__global__ void op_kernel(const float* __restrict__ oprl, const float* __restrict__ opil) {
    __shared__ __align__(16) float cs_s[8*256];
    __shared__ __align__(16) float ss_s[8*256];
    int tid = threadIdx.x, tBase = blockIdx.x*8;
    for (int i = tid; i < 8*256; i += 128) {
        int t = i >> 8, k = i & 255;
        cs_s[i] = g_cs[(tBase+t)*NFREQ + k];
        ss_s[i] = g_ss[(tBase+t)*NFREQ + k];
    }
    __syncthreads();
    int d = tid;
    float accr[8], acci[8];
    #pragma unroll
    for (int t = 0; t < 8; t++) { accr[t] = 0.f; acci[t] = 0.f; }
    for (int k = 0; k < 256; k += 4) {
        float4 wr = *reinterpret_cast<const float4*>(&oprl[d*256 + k]);
        float4 wi = *reinterpret_cast<const float4*>(&opil[d*256 + k]);
        #pragma unroll
        for (int t = 0; t < 8; t++) {
            accr[t] = fmaf(wr.x, cs_s[t*256+k+0], accr[t]);
            accr[t] = fmaf(wr.y, cs_s[t*256+k+1], accr[t]);
            accr[t] = fmaf(wr.z, cs_s[t*256+k+2], accr[t]);
            accr[t] = fmaf(wr.w, cs_s[t*256+k+3], accr[t]);
            acci[t] = fmaf(wi.x, ss_s[t*256+k+0], acci[t]);
            acci[t] = fmaf(wi.y, ss_s[t*256+k+1], acci[t]);
            acci[t] = fmaf(wi.z, ss_s[t*256+k+2], acci[t]);
            acci[t] = fmaf(wi.w, ss_s[t*256+k+3], acci[t]);
        }
    }
    #pragma unroll
    for (int t = 0; t < 8; t++) {
        float vr = accr[t], vi = acci[t];
        g_xr[(tBase+t)*DHID + d] = vr / (1.0f + expf(-vr));
        g_xi[(tBase+t)*DHID + d] = vi / (1.0f + expf(-vi));
    }
}

// ---------------- vocab GEMM: fp16 single-pass, A in registers, triple-buffered B ----------------
// CTA tile: M=128 x N=64, K=128. 8 warps = 4m x 2n; warp tile 32x32 (mf=2, nf=4).
// A fragments for all 8 k-steps hoisted into registers (A constant across all N-tiles).
// B (Wr, Wi) triple-buffered via cp.async; ONE __syncthreads per tile.
// lr = Ar*Wr - Ai*Wi (via XOR-to-temp) ; li = Ai*Wr + Ar*Wi
#define ROWB   272
#define A_MTX  (128*ROWB)        // 34816
#define B_MTX  (64*ROWB)         // 17408
#define B_BUF  (2*B_MTX)         // 34816 per stage
#define SMEM_A (2*A_MTX)         // 69632
#define GEMM_SMEM (SMEM_A + 3*B_BUF)  // 174080
#define TILE_N   64
#define NT_TOT   786
#define CHUNKS   18
#define NT_CHUNK 44

__device__ __forceinline__ void mma_f16(float c[4], const uint32_t a[4], const uint32_t b[2]) {
    asm volatile(
        "mma.sync.aligned.m16n8k16.row.col.f32.f16.f16.f32 "
        "{%0,%1,%2,%3}, {%4,%5,%6,%7}, {%8,%9}, {%0,%1,%2,%3};\n"
        : "+f"(c[0]), "+f"(c[1]), "+f"(c[2]), "+f"(c[3])
        : "r"(a[0]), "r"(a[1]), "r"(a[2]), "r"(a[3]), "r"(b[0]), "r"(b[1]));
}
__device__ __forceinline__ void ldsm_x4(uint32_t r[4], uint32_t addr) {
    asm volatile("ldmatrix.sync.aligned.m8n8.x4.shared.b16 {%0,%1,%2,%3}, [%4];\n"
                 : "=r"(r[0]), "=r"(r[1]), "=r"(r[2]), "=r"(r[3]) : "r"(addr));
}
__device__ __forceinline__ void cp16(uint32_t dst, const void* src, int sz) {
    asm volatile("cp.async.cg.shared.global [%0], [%1], 16, %2;\n"
                 :: "r"(dst), "l"(src), "r"(sz));
}
__device__ __forceinline__ void cp_commit() { asm volatile("cp.async.commit_group;\n"); }
__device__ __forceinline__ void cp_wait1()  { asm volatile("cp.async.wait_group 1;\n"); }

__device__ __forceinline__ void prefetch_b(uint32_t dstBase, int nBase, int tid) {
    // 2 matrices x 64 rows x 16 chunks(16B) = 2048 chunks; 8 per thread
    #pragma unroll
    for (int j = 0; j < 8; j++) {
        int idx = tid + j*256;
        int mtx = idx >> 10;
        int rem = idx & 1023;
        int r = rem >> 4, c = rem & 15;
        int v = nBase + r;
        int sz = (v < VOCAB) ? 16 : 0;
        int vc = (v < VOCAB) ? v : (VOCAB-1);
        const __half* s = (mtx == 0) ? g_Wr16 : g_Wi16;
        cp16(dstBase + mtx*B_MTX + r*ROWB + c*16,
             (const char*)(s + (size_t)vc*DHID) + c*16, sz);
    }
}

__global__ void __launch_bounds__(256, 1) gemm_hmma(float* __restrict__ out) {
    extern __shared__ __align__(16) char sm[];
    uint32_t sbase;
    asm("{ .reg .u64 t; cvta.to.shared.u64 t, %1; cvt.u32.u64 %0, t; }" : "=r"(sbase) : "l"(sm));

    const int tid = threadIdx.x;
    const int mBase = blockIdx.y * 128;
    const int ntStart = blockIdx.x * NT_CHUNK;
    int ntEnd = ntStart + NT_CHUNK; if (ntEnd > NT_TOT) ntEnd = NT_TOT;
    const int T = ntEnd - ntStart;
    if (T <= 0) return;

    // ---- group G0: A (Ar, Ai) + B tile 0 ----
    #pragma unroll
    for (int j = 0; j < 16; j++) {
        int idx = tid + j*256;
        int mtx = idx >> 11;
        int rem = idx & 2047;
        int r = rem >> 4, c = rem & 15;
        const __half* s = (mtx == 0) ? g_Ar16 : g_Ai16;
        cp16(sbase + mtx*A_MTX + r*ROWB + c*16,
             (const char*)(s + (size_t)(mBase + r)*DHID) + c*16, 16);
    }
    prefetch_b(sbase + SMEM_A, ntStart*TILE_N, tid);
    cp_commit();
    // ---- group G1: B tile 1 (zero-fill safe if beyond range) ----
    prefetch_b(sbase + SMEM_A + B_BUF, (ntStart + 1)*TILE_N, tid);
    cp_commit();

    const int warp = tid >> 5, lane = tid & 31;
    const int wm = warp >> 1, wn = warp & 1;
    const int g = lane >> 2, tg = lane & 3;

    // ldmatrix lane-address bases (verified mappings)
    uint32_t aAddr[2][2];   // [Ar/Ai][mf]
    {
        const int arow = (lane & 7) + (lane & 8);
        const int acol = (lane & 16) ? 16 : 0;
        #pragma unroll
        for (int mtx = 0; mtx < 2; mtx++)
            #pragma unroll
            for (int mf = 0; mf < 2; mf++)
                aAddr[mtx][mf] = sbase + mtx*A_MTX + (wm*32 + mf*16 + arow)*ROWB + acol;
    }
    uint32_t bAddr[2][2];   // [Wr/Wi][pair] relative to buffer 0
    {
        const int brow = (lane & 7) + ((lane & 16) ? 8 : 0);
        const int bcol = (lane & 8) ? 16 : 0;
        #pragma unroll
        for (int mtx = 0; mtx < 2; mtx++)
            #pragma unroll
            for (int p = 0; p < 2; p++)
                bAddr[mtx][p] = sbase + SMEM_A + mtx*B_MTX + (wn*32 + p*16 + brow)*ROWB + bcol;
    }

    // A fragments for all 8 k-steps, persistent in registers
    uint32_t Ar[2][8][4], Ai[2][8][4];   // [mf][ks][reg]

    for (int t = 0; t < T; t++) {
        // wait until tile t's cp group done (<=1 group pending), then CTA-wide visibility
        cp_wait1();
        __syncthreads();

        if (t == 0) {
            // A smem ready (G0): hoist all A fragments into registers, once
            #pragma unroll
            for (int mf = 0; mf < 2; mf++)
                #pragma unroll
                for (int ks = 0; ks < 8; ks++) {
                    ldsm_x4(Ar[mf][ks], aAddr[0][mf] + ks*32);
                    ldsm_x4(Ai[mf][ks], aAddr[1][mf] + ks*32);
                }
        }

        // prefetch tile t+2 into buf[(t+2)%3] (safe past range: zero-fill)
        prefetch_b(sbase + SMEM_A + ((t + 2) % 3)*B_BUF, (ntStart + t + 2)*TILE_N, tid);
        cp_commit();

        const uint32_t bufOff = (uint32_t)(t % 3)*B_BUF;

        float acc[2][2][4][4];   // [lr/li][mf][nf][q]
        #pragma unroll
        for (int o = 0; o < 2; o++)
            #pragma unroll
            for (int mf = 0; mf < 2; mf++)
                #pragma unroll
                for (int nf = 0; nf < 4; nf++)
                    #pragma unroll
                    for (int q = 0; q < 4; q++) acc[o][mf][nf][q] = 0.f;

        #pragma unroll
        for (int ks = 0; ks < 8; ks++) {
            const uint32_t kb = ks*32;
            uint32_t Wr[2][4], Wi[2][4];
            #pragma unroll
            for (int p = 0; p < 2; p++) {
                ldsm_x4(Wr[p], bAddr[0][p] + bufOff + kb);
                ldsm_x4(Wi[p], bAddr[1][p] + bufOff + kb);
            }
            #pragma unroll
            for (int mf = 0; mf < 2; mf++)
                #pragma unroll
                for (int nf = 0; nf < 4; nf++)
                    mma_f16(acc[0][mf][nf], Ar[mf][ks], &Wr[nf>>1][(nf&1)*2]);  // lr += Ar*Wr
            #pragma unroll
            for (int mf = 0; mf < 2; mf++)
                #pragma unroll
                for (int nf = 0; nf < 4; nf++)
                    mma_f16(acc[1][mf][nf], Ai[mf][ks], &Wr[nf>>1][(nf&1)*2]);  // li += Ai*Wr
            #pragma unroll
            for (int mf = 0; mf < 2; mf++)
                #pragma unroll
                for (int nf = 0; nf < 4; nf++)
                    mma_f16(acc[1][mf][nf], Ar[mf][ks], &Wi[nf>>1][(nf&1)*2]);  // li += Ar*Wi
            // negated-Ai temps (preserve persistent Ai regs)
            #pragma unroll
            for (int mf = 0; mf < 2; mf++) {
                uint32_t An[4];
                #pragma unroll
                for (int q = 0; q < 4; q++) An[q] = Ai[mf][ks][q] ^ 0x80008000u;
                #pragma unroll
                for (int nf = 0; nf < 4; nf++)
                    mma_f16(acc[0][mf][nf], An, &Wi[nf>>1][(nf&1)*2]);          // lr -= Ai*Wi
            }
        }

        // epilogue (scalar stores: VOCAB odd -> only 4B alignment guaranteed)
        const int nBase = (ntStart + t)*TILE_N;
        #pragma unroll
        for (int mf = 0; mf < 2; mf++) {
            const int row = mBase + wm*32 + mf*16 + g;
            #pragma unroll
            for (int nf = 0; nf < 4; nf++) {
                const int col = nBase + wn*32 + nf*8 + 2*tg;
                float* o0 = out + (size_t)row*VOCAB + col;
                float* o1 = o0 + (size_t)8*VOCAB;
                float lr0 = acc[0][mf][nf][0], li0 = acc[1][mf][nf][0];
                float lr1 = acc[0][mf][nf][1], li1 = acc[1][mf][nf][1];
                float lr2 = acc[0][mf][nf][2], li2 = acc[1][mf][nf][2];
                float lr3 = acc[0][mf][nf][3], li3 = acc[1][mf][nf][3];
                if (col < VOCAB) {
                    o0[0] = sqrtf(fmaf(lr0,lr0,fmaf(li0,li0,1e-8f)));
                    o1[0] = sqrtf(fmaf(lr2,lr2,fmaf(li2,li2,1e-8f)));
                }
                if (col + 1 < VOCAB) {
                    o0[1] = sqrtf(fmaf(lr1,lr1,fmaf(li1,li1,1e-8f)));
                    o1[1] = sqrtf(fmaf(lr3,lr3,fmaf(li3,li3,1e-8f)));
                }
            }
        }
        // no trailing sync: next iteration's top sync covers the WAR hazard
    }
}

// ---------------- launch ----------------
extern "C" void kernel_launch(void* const* d_in, const int* in_sizes, int n_in,
                              void* d_out, int out_size) {
    const int*   ids  = (const int*)  d_in[0];
    const float* emb  = (const float*)d_in[1];
    const float* cw   = (const float*)d_in[2];
    const float* cb   = (const float*)d_in[3];
    const float* W    = (const float*)d_in[4];
    const float* Bp   = (const float*)d_in[5];
    const float* acos_= (const float*)d_in[6];
    const float* asin_= (const float*)d_in[7];
    const float* opr  = (const float*)d_in[8];
    const float* opi  = (const float*)d_in[9];
    const float* Wr   = (const float*)d_in[10];
    const float* Wi   = (const float*)d_in[11];
    float* out = (float*)d_out;

    cudaFuncSetAttribute(gemm_hmma, cudaFuncAttributeMaxDynamicSharedMemorySize, GEMM_SMEM);

    embed_kernel<<<NTOK, 128>>>(ids, emb);
    wsplit_kernel<<<(VOCAB*DHID + 255)/256, 256>>>(Wr, Wi);

    for (int l = 0; l < 2; l++) {
        xc_kernel<<<NTOK/8, 128>>>(cw + (size_t)l*DHID*2*DHID, cb + (size_t)l*DHID);
        dim3 tg(NFREQ/4, NTOK/16);
        theta_kernel<<<tg, 128>>>(W + (size_t)l*NFREQ*DHID, Bp + (size_t)l*NFREQ*DHID,
                                  acos_ + (size_t)l*NFREQ*DHID, asin_ + (size_t)l*NFREQ*DHID);
        op_kernel<<<NTOK/8, 128>>>(opr + (size_t)l*DHID*NFREQ, opi + (size_t)l*DHID*NFREQ);
    }

    asplit_kernel<<<NTOK*DHID/256, 256>>>();
    gemm_hmma<<<dim3(CHUNKS, 8), 256, GEMM_SMEM>>>(out);
}